// round 5
// baseline (speedup 1.0000x reference)
#include <cuda_runtime.h>

#define SEQ  256
#define HID  2048
#define DIM  2048
#define NCTA 128
#define NTHR 1024
#define CH   8            // rows per pipeline chunk
#define NCH  10           // 80 rows / 8
#define CHF  (CH * DIM)   // floats per chunk (16384 = 64KB)

// ---- persistent device state (static allocation: allowed) ----
__device__ float g_Wp[(size_t)NCTA * DIM * 64];   // repacked W_ih: [b][j][64 owned rows]
__device__ __align__(16) float g_h[HID];
__device__ float g_x[DIM];
__device__ unsigned int g_bar;
__device__ volatile unsigned int g_gen;

// ---- JAX threefry2x32 (exact rounds, partitionable counter layout) ----
__device__ __forceinline__ void tf2x32(unsigned k0, unsigned k1,
                                       unsigned x0, unsigned x1,
                                       unsigned &o0, unsigned &o1) {
  unsigned ks2 = k0 ^ k1 ^ 0x1BD11BDAu;
#define TFR(r) { x0 += x1; x1 = (x1 << (r)) | (x1 >> (32 - (r))); x1 ^= x0; }
  x0 += k0; x1 += k1;
  TFR(13) TFR(15) TFR(26) TFR(6)   x0 += k1;  x1 += ks2 + 1u;
  TFR(17) TFR(29) TFR(16) TFR(24)  x0 += ks2; x1 += k0 + 2u;
  TFR(13) TFR(15) TFR(26) TFR(6)   x0 += k0;  x1 += k1 + 3u;
  TFR(17) TFR(29) TFR(16) TFR(24)  x0 += k1;  x1 += ks2 + 4u;
  TFR(13) TFR(15) TFR(26) TFR(6)   x0 += ks2; x1 += k0 + 5u;
#undef TFR
  o0 = x0; o1 = x1;
}

__device__ __forceinline__ float u01(unsigned bits) {
  return __uint_as_float((bits >> 9) | 0x3f800000u) - 1.0f;
}
__device__ __forceinline__ float sigf(float v) { return 1.0f / (1.0f + expf(-v)); }

__device__ __forceinline__ unsigned smem_u32(const void* p) {
  return (unsigned)__cvta_generic_to_shared(p);
}

// full grid barrier (all CTAs co-resident)
__device__ __forceinline__ void grid_barrier() {
  __threadfence();
  __syncthreads();
  if (threadIdx.x == 0) {
    unsigned gen = g_gen;
    if (atomicAdd(&g_bar, 1u) == gridDim.x - 1u) {
      g_bar = 0u; __threadfence(); g_gen = gen + 1u;
    } else {
      while (g_gen == gen) { __nanosleep(20); }
      __threadfence();
    }
  }
  __syncthreads();
}

// issue one 8-row chunk (64KB) of Phase-A weights via cp.async (one commit group)
__device__ __forceinline__ void issue_chunk(int c, float* buf, int b, int tid,
                                            const float* __restrict__ V_w,
                                            const float* __restrict__ W_hh) {
  const int rr  = tid >> 7;     // 0..7 row in chunk
  const int s16 = tid & 127;    // 128 threads per row
  const int gr  = c * CH + rr;  // virtual row 0..79
  const char* src;
  if (gr < 16) src = (const char*)(V_w + (size_t)(b * 16 + gr) * DIM);
  else {
    int gi = gr - 16;
    src = (const char*)(W_hh + (size_t)((gi >> 4) * HID + b * 16 + (gi & 15)) * DIM);
  }
  unsigned dst = smem_u32(buf + rr * DIM);
  #pragma unroll
  for (int it = 0; it < 4; ++it) {
    int off = (s16 + it * 128) * 16;  // bytes within 8KB row
    asm volatile("cp.async.cg.shared.global [%0], [%1], 16;\n"
                 :: "r"(dst + off), "l"(src + off));
  }
  asm volatile("cp.async.commit_group;\n");
}

extern "C" __global__ void __launch_bounds__(NTHR, 1)
lstm_policy_kernel(const float* __restrict__ A,
                   const float* __restrict__ W_ih,
                   const float* __restrict__ W_hh,
                   const float* __restrict__ b_ih,
                   const float* __restrict__ b_hh,
                   const float* __restrict__ V_w,
                   const float* __restrict__ V_b,
                   const float* __restrict__ temp,
                   float* __restrict__ out)
{
  extern __shared__ float dyn[];          // 2 x 64KB weight chunk buffers
  float* wbuf0 = dyn;
  float* wbuf1 = dyn + CHF;

  const int b    = blockIdx.x;
  const int tid  = threadIdx.x;
  const int lane = tid & 31;
  const int w    = tid >> 5;
  const int rr   = w >> 2;                // row-in-chunk this warp computes
  const int qt   = w & 3;                 // quarter of the 2048-dot

  __shared__ int   nzi[DIM];              // 8KB compacted indices
  __shared__ float nzv[DIM];              // 8KB compacted values
  __shared__ float2 part2[32][32];        // 8KB gather partials
  __shared__ float psum[CH][4];
  __shared__ float gsum[64];
  __shared__ float c_s[16];
  __shared__ int   wcnt[32];
  __shared__ int   woff[33];

  // ---- one-time repack: g_Wp[b][j][g] = W_ih[row(g)][j], row(g)=q*HID+b*16+i2 ----
  {
    float (*tile)[65] = (float(*)[65])dyn;  // 64x65 staging (aliases wbuf, pre-pipeline)
    for (int t = 0; t < 32; ++t) {
      int j0 = t * 64;
      #pragma unroll
      for (int gg = w; gg < 64; gg += 32) {
        int row = (gg >> 4) * HID + b * 16 + (gg & 15);
        #pragma unroll
        for (int jj = lane; jj < 64; jj += 32)
          tile[jj][gg] = W_ih[(size_t)row * DIM + j0 + jj];
      }
      __syncthreads();
      #pragma unroll
      for (int jj = w; jj < 64; jj += 32) {
        float* dst = &g_Wp[((size_t)b * DIM + j0 + jj) * 64];
        #pragma unroll
        for (int gg = lane; gg < 64; gg += 32) dst[gg] = tile[jj][gg];
      }
      __syncthreads();
    }
  }
  if (tid < 16) c_s[tid] = 0.0f;
  grid_barrier();

  const float temperature = __ldg(temp);

  // prologue: fill pipeline
  issue_chunk(0, wbuf0, b, tid, V_w, W_hh);
  issue_chunk(1, wbuf1, b, tid, V_w, W_hh);

  unsigned snap1 = 0;  // barrier-1 snapshot (tid 0 only)

  for (int step = 0; step < SEQ; ++step) {
    unsigned sk0, sk1;
    tf2x32(0u, 42u, 0u, (unsigned)step, sk0, sk1);

    // h segment for this warp's quarter, in registers
    float4 h0, h1, h2, h3;
    if (step == 0) {
      h0 = h1 = h2 = h3 = make_float4(0.f, 0.f, 0.f, 0.f);
    } else {
      const float4* gh4 = (const float4*)g_h + qt * 128 + lane;
      h0 = __ldcg(gh4); h1 = __ldcg(gh4 + 32); h2 = __ldcg(gh4 + 64); h3 = __ldcg(gh4 + 96);
    }

    // ====== Phase A: pipelined chunks (rows 0..15 V_w -> pi/x; 16..79 W_hh -> gsum) ======
    for (int c = 0; c < NCH; ++c) {
      if (c >= 1 && c + 1 < NCH)
        issue_chunk(c + 1, ((c + 1) & 1) ? wbuf1 : wbuf0, b, tid, V_w, W_hh);
      if (c + 1 < NCH) asm volatile("cp.async.wait_group 1;\n");
      else             asm volatile("cp.async.wait_group 0;\n");
      __syncthreads();   // chunk c visible; previous compute done

      {
        const float4* wr = (const float4*)(((c & 1) ? wbuf1 : wbuf0) + rr * DIM)
                           + qt * 128 + lane;
        float4 a0 = wr[0], a1 = wr[32], a2 = wr[64], a3 = wr[96];
        float s = a0.x * h0.x + a0.y * h0.y + a0.z * h0.z + a0.w * h0.w;
        s += a1.x * h1.x + a1.y * h1.y + a1.z * h1.z + a1.w * h1.w;
        s += a2.x * h2.x + a2.y * h2.y + a2.z * h2.z + a2.w * h2.w;
        s += a3.x * h3.x + a3.y * h3.y + a3.z * h3.z + a3.w * h3.w;
        #pragma unroll
        for (int o = 16; o > 0; o >>= 1) s += __shfl_xor_sync(0xffffffffu, s, o);
        if (lane == 0) psum[rr][qt] = s;
      }
      __syncthreads();   // psum ready

      if (tid < CH) {
        float sv = ((psum[tid][0] + psum[tid][1]) + psum[tid][2]) + psum[tid][3];
        int gr = c * CH + tid;
        if (gr < 16) {
          int r = b * 16 + gr;
          float z  = temperature * (sv + __ldg(&V_b[r]));
          float pi = sigf(z);
          unsigned y0, y1;
          tf2x32(sk0, sk1, 0u, (unsigned)r, y0, y1);
          float u   = u01(y0 ^ y1);
          float act = (u < pi) ? 1.0f : 0.0f;
          __stcs(&out[(size_t)step * DIM + r], act);
          __stcs(&out[(size_t)SEQ * DIM + (size_t)step * DIM + r], pi);
          __stcg(&g_x[r], act * __ldg(&A[r]));
        } else {
          int gi = gr - 16;
          int row = (gi >> 4) * HID + b * 16 + (gi & 15);
          gsum[gi] = sv + __ldg(&b_ih[row]) + __ldg(&b_hh[row]);
        }
      }
      if (c == 1) __threadfence();   // x writers' stores globally visible
      __syncthreads();               // dispatch done; buffers safe for reuse
      if (c == 1 && tid == 0) {      // barrier-1 ARRIVE (wait happens later)
        snap1 = g_gen;
        if (atomicAdd(&g_bar, 1u) == NCTA - 1u) {
          g_bar = 0u; __threadfence(); g_gen = snap1 + 1u;
        }
      }
    }

    // prefetch next step's first two chunks (weights are step-invariant)
    if (step + 1 < SEQ) {
      issue_chunk(0, wbuf0, b, tid, V_w, W_hh);
      issue_chunk(1, wbuf1, b, tid, V_w, W_hh);
    }

    // barrier-1 WAIT: all CTAs' x written
    if (tid == 0) {
      while (g_gen == snap1) { __nanosleep(20); }
      __threadfence();
    }
    __syncthreads();

    // ====== Phase B: compact nonzeros of x, gather repacked W_ih, cell update ======
    {
      int base = w * 64;
      float v0 = __ldcg(&g_x[base + lane]);
      float v1 = __ldcg(&g_x[base + 32 + lane]);
      unsigned b0 = __ballot_sync(0xffffffffu, v0 != 0.0f);
      unsigned b1 = __ballot_sync(0xffffffffu, v1 != 0.0f);
      if (lane == 0) wcnt[w] = __popc(b0) + __popc(b1);
      __syncthreads();
      if (w == 0) {
        int c2 = wcnt[lane];
        int xs = c2;
        #pragma unroll
        for (int o = 1; o < 32; o <<= 1) {
          int y = __shfl_up_sync(0xffffffffu, xs, o);
          if (lane >= o) xs += y;
        }
        woff[lane] = xs - c2;
        if (lane == 31) woff[32] = xs;
      }
      __syncthreads();
      int off = woff[w];
      unsigned mlo = (1u << lane) - 1u;
      if (v0 != 0.0f) { int p = off + __popc(b0 & mlo); nzi[p] = base + lane; nzv[p] = v0; }
      if (v1 != 0.0f) { int p = off + __popc(b0) + __popc(b1 & mlo); nzi[p] = base + 32 + lane; nzv[p] = v1; }
      __syncthreads();
    }
    const int len = woff[32];

    {
      const int seg = tid >> 5, g2 = tid & 31;
      const float2* wp2 = (const float2*)g_Wp + (size_t)b * (DIM * 32) + g2;
      float acc0 = 0.0f, acc1 = 0.0f;
      #pragma unroll 4
      for (int k = seg; k < len; k += 32) {
        float2 wv = __ldcs(wp2 + (size_t)nzi[k] * 32);
        float xv = nzv[k];
        acc0 = fmaf(xv, wv.x, acc0);
        acc1 = fmaf(xv, wv.y, acc1);
      }
      part2[seg][g2] = make_float2(acc0, acc1);
    }
    __syncthreads();
    if (tid < 64) {
      float s2 = gsum[tid];
      const int gp  = tid >> 1;
      const int odd = tid & 1;
      #pragma unroll
      for (int s3 = 0; s3 < 32; ++s3) {
        float2 pv = part2[s3][gp];
        s2 += odd ? pv.y : pv.x;
      }
      gsum[tid] = s2;
    }
    __syncthreads();

    if (tid < 16) {
      float ig = gsum[tid];
      float fg = gsum[16 + tid];
      float gg = gsum[32 + tid];
      float og = gsum[48 + tid];
      float cn = sigf(fg) * c_s[tid] + sigf(ig) * tanhf(gg);
      float hn = sigf(og) * tanhf(cn);
      c_s[tid] = cn;
      __stcg(&g_h[b * 16 + tid], hn);
    }
    grid_barrier();   // h visible for next step
  }
}

extern "C" void kernel_launch(void* const* d_in, const int* in_sizes, int n_in,
                              void* d_out, int out_size) {
  (void)in_sizes; (void)n_in; (void)out_size;
  static int configured = 0;
  if (!configured) {
    cudaFuncSetAttribute(lstm_policy_kernel,
                         cudaFuncAttributeMaxDynamicSharedMemorySize, 2 * CHF * 4);
    configured = 1;
  }
  lstm_policy_kernel<<<NCTA, NTHR, 2 * CHF * 4>>>(
      (const float*)d_in[0],  // A
      (const float*)d_in[1],  // W_ih
      (const float*)d_in[2],  // W_hh
      (const float*)d_in[3],  // b_ih
      (const float*)d_in[4],  // b_hh
      (const float*)d_in[5],  // V_w
      (const float*)d_in[6],  // V_b
      (const float*)d_in[7],  // temperature
      (float*)d_out);
}

// round 6
// speedup vs baseline: 1.5376x; 1.5376x over previous
#include <cuda_runtime.h>

#define SEQ  256
#define HID  2048
#define DIM  2048
#define NCTA 128
#define NTHR 1024
#define PJ   640                      // gather columns pinned in smem
#define DYNB (PJ * 64 * 4)            // 163840 bytes dynamic smem

// ---- persistent device state (static allocation: allowed) ----
__device__ float g_Wp[(size_t)NCTA * DIM * 64];   // repacked W_ih: [b][j][64 owned rows]
__device__ __align__(16) float g_h[HID];
__device__ float g_x[DIM];
__device__ volatile unsigned g_c0 = 0;            // barrier channel 0 (x-ready), monotonic
__device__ volatile unsigned g_c1 = 0;            // barrier channel 1 (h-ready), monotonic

// ---- JAX threefry2x32 (exact rounds, partitionable counter layout) ----
__device__ __forceinline__ void tf2x32(unsigned k0, unsigned k1,
                                       unsigned x0, unsigned x1,
                                       unsigned &o0, unsigned &o1) {
  unsigned ks2 = k0 ^ k1 ^ 0x1BD11BDAu;
#define TFR(r) { x0 += x1; x1 = (x1 << (r)) | (x1 >> (32 - (r))); x1 ^= x0; }
  x0 += k0; x1 += k1;
  TFR(13) TFR(15) TFR(26) TFR(6)   x0 += k1;  x1 += ks2 + 1u;
  TFR(17) TFR(29) TFR(16) TFR(24)  x0 += ks2; x1 += k0 + 2u;
  TFR(13) TFR(15) TFR(26) TFR(6)   x0 += k0;  x1 += k1 + 3u;
  TFR(17) TFR(29) TFR(16) TFR(24)  x0 += k1;  x1 += ks2 + 4u;
  TFR(13) TFR(15) TFR(26) TFR(6)   x0 += ks2; x1 += k0 + 5u;
#undef TFR
  o0 = x0; o1 = x1;
}

__device__ __forceinline__ float u01(unsigned bits) {
  return __uint_as_float((bits >> 9) | 0x3f800000u) - 1.0f;
}
__device__ __forceinline__ float sigf(float v) { return 1.0f / (1.0f + expf(-v)); }

extern "C" __global__ void __launch_bounds__(NTHR, 1)
lstm_policy_kernel(const float* __restrict__ A,
                   const float* __restrict__ W_ih,
                   const float* __restrict__ W_hh,
                   const float* __restrict__ b_ih,
                   const float* __restrict__ b_hh,
                   const float* __restrict__ V_w,
                   const float* __restrict__ V_b,
                   const float* __restrict__ temp,
                   float* __restrict__ out)
{
  extern __shared__ float pinW[];     // [PJ][64] pinned gather columns (160KB)

  const int b    = blockIdx.x;
  const int tid  = threadIdx.x;
  const int lane = tid & 31;
  const int w    = tid >> 5;

  __shared__ float h_s[HID];          // 8KB
  __shared__ int   nzi[DIM];          // 8KB
  __shared__ float nzv[DIM];          // 8KB
  __shared__ float2 part2[32][32];    // 8KB
  __shared__ float psumV[16][2];
  __shared__ float psumP[32];
  __shared__ float psumL[32];
  __shared__ float gsum[64];
  __shared__ float c_s[16];
  __shared__ int   wcnt[32];
  __shared__ int   woff[33];

  // ---- one-time repack: g_Wp[b][j][g] = W_ih[row(g)][j] (pinW aliased as staging) ----
  {
    float (*tile)[65] = (float(*)[65])pinW;   // 64x65 staging
    for (int t = 0; t < 32; ++t) {
      int j0 = t * 64;
      for (int gg = w; gg < 64; gg += 32) {
        int row = (gg >> 4) * HID + b * 16 + (gg & 15);
        for (int jj = lane; jj < 64; jj += 32)
          tile[jj][gg] = W_ih[(size_t)row * DIM + j0 + jj];
      }
      __syncthreads();
      for (int jj = w; jj < 64; jj += 32) {
        float* dst = &g_Wp[((size_t)b * DIM + j0 + jj) * 64];
        for (int gg = lane; gg < 64; gg += 32) dst[gg] = tile[jj][gg];
      }
      __syncthreads();
    }
    // fill pinned gather region from own repacked slice (contiguous copy)
    const float* src = &g_Wp[(size_t)b * DIM * 64];
    for (int i = tid; i < PJ * 64; i += NTHR) pinW[i] = src[i];
  }
  if (tid < 16) c_s[tid] = 0.0f;

  // ---- register-pin one W_hh row per warp: gate pg = w (gates 0..31) ----
  float4 pin[16];
  {
    int row = (w >> 4) * HID + b * 16 + (w & 15);
    const float4* rp = (const float4*)(W_hh + (size_t)row * DIM);
    #pragma unroll
    for (int k = 0; k < 16; ++k) pin[k] = __ldg(rp + k * 32 + lane);
  }
  __syncthreads();

  const float temperature = __ldg(temp);
  const float4* H4 = (const float4*)h_s;

  for (int step = 0; step < SEQ; ++step) {
    unsigned sk0, sk1;
    tf2x32(0u, 42u, 0u, (unsigned)step, sk0, sk1);

    // load h into smem
    for (int i = tid; i < HID; i += NTHR)
      h_s[i] = (step == 0) ? 0.0f : __ldcg(&g_h[i]);
    __syncthreads();

    // ====== Phase A1: V_w rows as half-dots (fast x publication) ======
    {
      int r16 = w >> 1, hf = w & 1;
      const float4* R  = (const float4*)(V_w + (size_t)(b * 16 + r16) * DIM) + hf * 256;
      const float4* Hh = H4 + hf * 256;
      float s = 0.0f;
      #pragma unroll
      for (int k = 0; k < 8; ++k) {
        float4 a  = __ldg(R + k * 32 + lane);
        float4 hh = Hh[k * 32 + lane];
        s += a.x * hh.x + a.y * hh.y + a.z * hh.z + a.w * hh.w;
      }
      #pragma unroll
      for (int o = 16; o > 0; o >>= 1) s += __shfl_xor_sync(0xffffffffu, s, o);
      if (lane == 0) psumV[r16][hf] = s;
    }
    __syncthreads();
    if (tid < 16) {
      float sv = psumV[tid][0] + psumV[tid][1];
      int r = b * 16 + tid;
      float z  = temperature * (sv + __ldg(&V_b[r]));
      float pi = sigf(z);
      unsigned y0, y1;
      tf2x32(sk0, sk1, 0u, (unsigned)r, y0, y1);
      float u   = u01(y0 ^ y1);
      float act = (u < pi) ? 1.0f : 0.0f;
      __stcs(&out[(size_t)step * DIM + r], act);
      __stcs(&out[(size_t)SEQ * DIM + (size_t)step * DIM + r], pi);
      __stcg(&g_x[r], act * __ldg(&A[r]));
    }
    __threadfence();
    __syncthreads();
    if (tid == 0) atomicAdd((unsigned*)&g_c0, 1u);   // barrier-1 ARRIVE (hidden)

    // ====== Phase A2: W_hh — 1 pinned (gate w) + 1 loaded (gate 32+w) row per warp ======
    {
      int lg = 32 + w;
      int row = (lg >> 4) * HID + b * 16 + (lg & 15);
      const float4* R = (const float4*)(W_hh + (size_t)row * DIM);
      float sL = 0.0f, sP = 0.0f;
      #pragma unroll
      for (int k = 0; k < 16; ++k) {
        float4 a  = __ldg(R + k * 32 + lane);
        float4 hh = H4[k * 32 + lane];
        sL += a.x * hh.x + a.y * hh.y + a.z * hh.z + a.w * hh.w;
        sP += pin[k].x * hh.x + pin[k].y * hh.y + pin[k].z * hh.z + pin[k].w * hh.w;
      }
      #pragma unroll
      for (int o = 16; o > 0; o >>= 1) {
        sL += __shfl_xor_sync(0xffffffffu, sL, o);
        sP += __shfl_xor_sync(0xffffffffu, sP, o);
      }
      if (lane == 0) { psumL[w] = sL; psumP[w] = sP; }
    }
    __syncthreads();
    if (tid < 64) {
      float sv = (tid < 32) ? psumP[tid] : psumL[tid - 32];
      int row = (tid >> 4) * HID + b * 16 + (tid & 15);
      gsum[tid] = sv + __ldg(&b_ih[row]) + __ldg(&b_hh[row]);
    }

    // barrier-1 WAIT: all CTAs' x written
    if (tid == 0) {
      unsigned tgt = (unsigned)NCTA * (unsigned)(step + 1);
      while (g_c0 < tgt) { }
      __threadfence();
    }
    __syncthreads();

    // ====== Phase B: compact nonzeros of x, split smem/global gather ======
    {
      int base = w * 64;
      float v0 = __ldcg(&g_x[base + lane]);
      float v1 = __ldcg(&g_x[base + 32 + lane]);
      unsigned b0 = __ballot_sync(0xffffffffu, v0 != 0.0f);
      unsigned b1 = __ballot_sync(0xffffffffu, v1 != 0.0f);
      if (lane == 0) wcnt[w] = __popc(b0) + __popc(b1);
      __syncthreads();
      if (w == 0) {
        int c2 = wcnt[lane];
        int xs = c2;
        #pragma unroll
        for (int o = 1; o < 32; o <<= 1) {
          int y = __shfl_up_sync(0xffffffffu, xs, o);
          if (lane >= o) xs += y;
        }
        woff[lane] = xs - c2;
        if (lane == 31) woff[32] = xs;
      }
      __syncthreads();
      int off = woff[w];
      unsigned mlo = (1u << lane) - 1u;
      if (v0 != 0.0f) { int p = off + __popc(b0 & mlo); nzi[p] = base + lane; nzv[p] = v0; }
      if (v1 != 0.0f) { int p = off + __popc(b0) + __popc(b1 & mlo); nzi[p] = base + 32 + lane; nzv[p] = v1; }
      __syncthreads();
    }
    const int len  = woff[32];
    const int len0 = woff[PJ / 64];   // nonzeros with j < PJ (smem-pinned prefix)

    {
      const int seg = tid >> 5, g2 = tid & 31;
      const float2* wp2  = (const float2*)g_Wp + (size_t)b * (DIM * 32) + g2;
      const float2* pin2 = (const float2*)pinW + g2;
      // contiguous k-block per segment
      int kb0 = (len * seg) >> 5;
      int kb1 = (len * (seg + 1)) >> 5;
      float acc0 = 0.0f, acc1 = 0.0f;
      int ks = kb1 < len0 ? kb1 : len0;
      for (int k = kb0; k < ks; ++k) {                 // smem-pinned part
        float2 wv = pin2[(size_t)nzi[k] * 32];
        float xv = nzv[k];
        acc0 = fmaf(xv, wv.x, acc0);
        acc1 = fmaf(xv, wv.y, acc1);
      }
      int kg = kb0 > len0 ? kb0 : len0;
      #pragma unroll 4
      for (int k = kg; k < kb1; ++k) {                 // global streaming part
        float2 wv = __ldcs(wp2 + (size_t)nzi[k] * 32);
        float xv = nzv[k];
        acc0 = fmaf(xv, wv.x, acc0);
        acc1 = fmaf(xv, wv.y, acc1);
      }
      part2[seg][g2] = make_float2(acc0, acc1);
    }
    __syncthreads();
    if (tid < 64) {
      float s2 = gsum[tid];
      const int gp  = tid >> 1;
      const int odd = tid & 1;
      #pragma unroll
      for (int s3 = 0; s3 < 32; ++s3) {
        float2 pv = part2[s3][gp];
        s2 += odd ? pv.y : pv.x;
      }
      gsum[tid] = s2;
    }
    __syncthreads();

    if (tid < 16) {
      float ig = gsum[tid];
      float fg = gsum[16 + tid];
      float gg = gsum[32 + tid];
      float og = gsum[48 + tid];
      float cn = sigf(fg) * c_s[tid] + sigf(ig) * tanhf(gg);
      float hn = sigf(og) * tanhf(cn);
      c_s[tid] = cn;
      __stcg(&g_h[b * 16 + tid], hn);
    }
    __threadfence();
    __syncthreads();
    if (tid == 0) {                                    // barrier-2 arrive + wait
      atomicAdd((unsigned*)&g_c1, 1u);
      unsigned tgt = (unsigned)NCTA * (unsigned)(step + 1);
      while (g_c1 < tgt) { }
      __threadfence();
    }
    __syncthreads();
  }

  // ---- exit barrier + counter reset (keeps graph replays correct) ----
  __syncthreads();
  if (tid == 0) {
    atomicAdd((unsigned*)&g_c0, 1u);
    if (b == 0) {
      unsigned tgt = (unsigned)NCTA * (unsigned)SEQ + (unsigned)NCTA;
      while (g_c0 < tgt) { }
      g_c0 = 0u;
      g_c1 = 0u;
      __threadfence();
    }
  }
}

extern "C" void kernel_launch(void* const* d_in, const int* in_sizes, int n_in,
                              void* d_out, int out_size) {
  (void)in_sizes; (void)n_in; (void)out_size;
  cudaFuncSetAttribute(lstm_policy_kernel,
                       cudaFuncAttributeMaxDynamicSharedMemorySize, DYNB);
  lstm_policy_kernel<<<NCTA, NTHR, DYNB>>>(
      (const float*)d_in[0],  // A
      (const float*)d_in[1],  // W_ih
      (const float*)d_in[2],  // W_hh
      (const float*)d_in[3],  // b_ih
      (const float*)d_in[4],  // b_hh
      (const float*)d_in[5],  // V_w
      (const float*)d_in[6],  // V_b
      (const float*)d_in[7],  // temperature
      (float*)d_out);
}

// round 7
// speedup vs baseline: 1.8364x; 1.1943x over previous
#include <cuda_runtime.h>

#define SEQ  256
#define HID  2048
#define DIM  2048
#define NCTA 128
#define NTHR 1024
#define PJ   640                      // gather columns pinned in smem
#define DYNB (PJ * 64 * 4)            // 163840 bytes dynamic smem

// ---- persistent device state (static allocation: allowed) ----
__device__ float g_Wp[(size_t)NCTA * DIM * 64];   // repacked W_ih: [b][j][64 owned rows]
__device__ __align__(16) float g_h[HID];
__device__ float g_x[DIM];
__device__ volatile unsigned g_c0 = 0;            // barrier channel 0 (x-ready), monotonic
__device__ volatile unsigned g_c1 = 0;            // barrier channel 1 (h-ready), monotonic

// ---- JAX threefry2x32 (exact rounds, partitionable counter layout) ----
__device__ __forceinline__ void tf2x32(unsigned k0, unsigned k1,
                                       unsigned x0, unsigned x1,
                                       unsigned &o0, unsigned &o1) {
  unsigned ks2 = k0 ^ k1 ^ 0x1BD11BDAu;
#define TFR(r) { x0 += x1; x1 = (x1 << (r)) | (x1 >> (32 - (r))); x1 ^= x0; }
  x0 += k0; x1 += k1;
  TFR(13) TFR(15) TFR(26) TFR(6)   x0 += k1;  x1 += ks2 + 1u;
  TFR(17) TFR(29) TFR(16) TFR(24)  x0 += ks2; x1 += k0 + 2u;
  TFR(13) TFR(15) TFR(26) TFR(6)   x0 += k0;  x1 += k1 + 3u;
  TFR(17) TFR(29) TFR(16) TFR(24)  x0 += k1;  x1 += ks2 + 4u;
  TFR(13) TFR(15) TFR(26) TFR(6)   x0 += ks2; x1 += k0 + 5u;
#undef TFR
  o0 = x0; o1 = x1;
}

__device__ __forceinline__ float u01(unsigned bits) {
  return __uint_as_float((bits >> 9) | 0x3f800000u) - 1.0f;
}
__device__ __forceinline__ float sigf(float v) { return 1.0f / (1.0f + expf(-v)); }

extern "C" __global__ void __launch_bounds__(NTHR, 1)
lstm_policy_kernel(const float* __restrict__ A,
                   const float* __restrict__ W_ih,
                   const float* __restrict__ W_hh,
                   const float* __restrict__ b_ih,
                   const float* __restrict__ b_hh,
                   const float* __restrict__ V_w,
                   const float* __restrict__ V_b,
                   const float* __restrict__ temp,
                   float* __restrict__ out)
{
  extern __shared__ float pinW[];     // [PJ][64] pinned gather columns (160KB)

  const int b    = blockIdx.x;
  const int tid  = threadIdx.x;
  const int lane = tid & 31;
  const int w    = tid >> 5;

  __shared__ float h_s[HID];          // 8KB
  __shared__ int   nzi[DIM];          // 8KB
  __shared__ float nzv[DIM];          // 8KB
  __shared__ float4 part4[64][16];    // 16KB gather partials [seg][gate-quad]
  __shared__ float psumV[16][2];
  __shared__ float2 psum2[32];
  __shared__ float gsum[64];
  __shared__ float c_s[16];
  __shared__ int   wcnt[32];
  __shared__ int   woff[33];

  // ---- one-time repack: g_Wp[b][j][g] = W_ih[row(g)][j] (pinW aliased as staging) ----
  {
    float (*tile)[65] = (float(*)[65])pinW;   // 64x65 staging
    for (int t = 0; t < 32; ++t) {
      int j0 = t * 64;
      for (int gg = w; gg < 64; gg += 32) {
        int row = (gg >> 4) * HID + b * 16 + (gg & 15);
        for (int jj = lane; jj < 64; jj += 32)
          tile[jj][gg] = W_ih[(size_t)row * DIM + j0 + jj];
      }
      __syncthreads();
      for (int jj = w; jj < 64; jj += 32) {
        float* dst = &g_Wp[((size_t)b * DIM + j0 + jj) * 64];
        for (int gg = lane; gg < 64; gg += 32) dst[gg] = tile[jj][gg];
      }
      __syncthreads();
    }
    // fill pinned gather region from own repacked slice (contiguous copy)
    const float* src = &g_Wp[(size_t)b * DIM * 64];
    for (int i = tid; i < PJ * 64; i += NTHR) pinW[i] = src[i];
  }
  if (tid < 16) c_s[tid] = 0.0f;
  __syncthreads();

  const float temperature = __ldg(temp);
  const float4* H4 = (const float4*)h_s;

  for (int step = 0; step < SEQ; ++step) {
    unsigned sk0, sk1;
    tf2x32(0u, 42u, 0u, (unsigned)step, sk0, sk1);

    // load h into smem
    for (int i = tid; i < HID; i += NTHR)
      h_s[i] = (step == 0) ? 0.0f : __ldcg(&g_h[i]);
    __syncthreads();

    // ====== Phase A1: V_w rows as half-dots (fast x publication) ======
    {
      int r16 = w >> 1, hf = w & 1;
      const float4* R  = (const float4*)(V_w + (size_t)(b * 16 + r16) * DIM) + hf * 256;
      const float4* Hh = H4 + hf * 256;
      float s = 0.0f;
      #pragma unroll
      for (int k = 0; k < 8; ++k) {
        float4 a  = __ldg(R + k * 32 + lane);
        float4 hh = Hh[k * 32 + lane];
        s += a.x * hh.x + a.y * hh.y + a.z * hh.z + a.w * hh.w;
      }
      #pragma unroll
      for (int o = 16; o > 0; o >>= 1) s += __shfl_xor_sync(0xffffffffu, s, o);
      if (lane == 0) psumV[r16][hf] = s;
    }
    __syncthreads();
    if (tid < 16) {
      float sv = psumV[tid][0] + psumV[tid][1];
      int r = b * 16 + tid;
      float z  = temperature * (sv + __ldg(&V_b[r]));
      float pi = sigf(z);
      unsigned y0, y1;
      tf2x32(sk0, sk1, 0u, (unsigned)r, y0, y1);
      float u   = u01(y0 ^ y1);
      float act = (u < pi) ? 1.0f : 0.0f;
      __stcs(&out[(size_t)step * DIM + r], act);
      __stcs(&out[(size_t)SEQ * DIM + (size_t)step * DIM + r], pi);
      __stcg(&g_x[r], act * __ldg(&A[r]));
    }
    __threadfence();
    __syncthreads();
    if (tid == 0) atomicAdd((unsigned*)&g_c0, 1u);   // barrier-1 ARRIVE (hidden)

    // ====== Phase A2: W_hh — 2 rows per warp (gates w, 32+w), 2 accumulators ======
    {
      int rowA = (w >> 4) * HID + b * 16 + (w & 15);
      int lg = 32 + w;
      int rowB = (lg >> 4) * HID + b * 16 + (lg & 15);
      const float4* RA = (const float4*)(W_hh + (size_t)rowA * DIM);
      const float4* RB = (const float4*)(W_hh + (size_t)rowB * DIM);
      float sA = 0.0f, sB = 0.0f;
      #pragma unroll
      for (int k = 0; k < 16; ++k) {
        float4 a  = __ldg(RA + k * 32 + lane);
        float4 bb = __ldg(RB + k * 32 + lane);
        float4 hh = H4[k * 32 + lane];
        sA += a.x  * hh.x + a.y  * hh.y + a.z  * hh.z + a.w  * hh.w;
        sB += bb.x * hh.x + bb.y * hh.y + bb.z * hh.z + bb.w * hh.w;
      }
      #pragma unroll
      for (int o = 16; o > 0; o >>= 1) {
        sA += __shfl_xor_sync(0xffffffffu, sA, o);
        sB += __shfl_xor_sync(0xffffffffu, sB, o);
      }
      if (lane == 0) psum2[w] = make_float2(sA, sB);
    }
    __syncthreads();
    if (tid < 64) {
      float sv = (tid < 32) ? psum2[tid].x : psum2[tid - 32].y;
      int row = (tid >> 4) * HID + b * 16 + (tid & 15);
      gsum[tid] = sv + __ldg(&b_ih[row]) + __ldg(&b_hh[row]);
    }

    // barrier-1 WAIT: all CTAs' x written
    if (tid == 0) {
      unsigned tgt = (unsigned)NCTA * (unsigned)(step + 1);
      while (g_c0 < tgt) { }
      __threadfence();
    }
    __syncthreads();

    // ====== Phase B: compact nonzeros of x, split smem/global float4 gather ======
    {
      int base = w * 64;
      float v0 = __ldcg(&g_x[base + lane]);
      float v1 = __ldcg(&g_x[base + 32 + lane]);
      unsigned b0 = __ballot_sync(0xffffffffu, v0 != 0.0f);
      unsigned b1 = __ballot_sync(0xffffffffu, v1 != 0.0f);
      if (lane == 0) wcnt[w] = __popc(b0) + __popc(b1);
      __syncthreads();
      if (w == 0) {
        int c2 = wcnt[lane];
        int xs = c2;
        #pragma unroll
        for (int o = 1; o < 32; o <<= 1) {
          int y = __shfl_up_sync(0xffffffffu, xs, o);
          if (lane >= o) xs += y;
        }
        woff[lane] = xs - c2;
        if (lane == 31) woff[32] = xs;
      }
      __syncthreads();
      int off = woff[w];
      unsigned mlo = (1u << lane) - 1u;
      if (v0 != 0.0f) { int p = off + __popc(b0 & mlo); nzi[p] = base + lane; nzv[p] = v0; }
      if (v1 != 0.0f) { int p = off + __popc(b0) + __popc(b1 & mlo); nzi[p] = base + 32 + lane; nzv[p] = v1; }
      __syncthreads();
    }
    const int len  = woff[32];
    const int len0 = woff[PJ / 64];   // nonzeros with j < PJ (smem-pinned prefix)

    {
      const int seg = tid >> 4;           // 64 segments
      const int g4  = tid & 15;           // gate quad (4 gates per thread)
      const float4* wp4  = (const float4*)g_Wp + (size_t)b * (DIM * 16) + g4;
      const float4* pin4 = (const float4*)pinW + g4;
      int kb0 = (len * seg) >> 6;
      int kb1 = (len * (seg + 1)) >> 6;
      float4 acc = make_float4(0.f, 0.f, 0.f, 0.f);
      int ks = kb1 < len0 ? kb1 : len0;
      #pragma unroll 4
      for (int k = kb0; k < ks; ++k) {                 // smem-pinned part
        float4 wv = pin4[(size_t)nzi[k] * 16];
        float xv = nzv[k];
        acc.x = fmaf(xv, wv.x, acc.x);
        acc.y = fmaf(xv, wv.y, acc.y);
        acc.z = fmaf(xv, wv.z, acc.z);
        acc.w = fmaf(xv, wv.w, acc.w);
      }
      int kg = kb0 > len0 ? kb0 : len0;
      #pragma unroll 8
      for (int k = kg; k < kb1; ++k) {                 // global streaming part
        float4 wv = __ldcs(wp4 + (size_t)nzi[k] * 16);
        float xv = nzv[k];
        acc.x = fmaf(xv, wv.x, acc.x);
        acc.y = fmaf(xv, wv.y, acc.y);
        acc.z = fmaf(xv, wv.z, acc.z);
        acc.w = fmaf(xv, wv.w, acc.w);
      }
      part4[seg][g4] = acc;
    }
    __syncthreads();
    if (tid < 64) {
      float s2 = gsum[tid];
      const int gp = tid >> 2, comp = tid & 3;
      const float* pp = (const float*)&part4[0][gp] + comp;
      #pragma unroll
      for (int s3 = 0; s3 < 64; ++s3) s2 += pp[(size_t)s3 * 64];
      gsum[tid] = s2;
    }
    __syncthreads();

    if (tid < 16) {
      float ig = gsum[tid];
      float fg = gsum[16 + tid];
      float gg = gsum[32 + tid];
      float og = gsum[48 + tid];
      float cn = sigf(fg) * c_s[tid] + sigf(ig) * tanhf(gg);
      float hn = sigf(og) * tanhf(cn);
      c_s[tid] = cn;
      __stcg(&g_h[b * 16 + tid], hn);
    }
    __threadfence();
    __syncthreads();
    if (tid == 0) {                                    // barrier-2 arrive + wait
      atomicAdd((unsigned*)&g_c1, 1u);
      unsigned tgt = (unsigned)NCTA * (unsigned)(step + 1);
      while (g_c1 < tgt) { }
      __threadfence();
    }
    __syncthreads();
  }

  // ---- exit barrier + counter reset (keeps graph replays correct) ----
  __syncthreads();
  if (tid == 0) {
    atomicAdd((unsigned*)&g_c0, 1u);
    if (b == 0) {
      unsigned tgt = (unsigned)NCTA * (unsigned)SEQ + (unsigned)NCTA;
      while (g_c0 < tgt) { }
      g_c0 = 0u;
      g_c1 = 0u;
      __threadfence();
    }
  }
}

extern "C" void kernel_launch(void* const* d_in, const int* in_sizes, int n_in,
                              void* d_out, int out_size) {
  (void)in_sizes; (void)n_in; (void)out_size;
  cudaFuncSetAttribute(lstm_policy_kernel,
                       cudaFuncAttributeMaxDynamicSharedMemorySize, DYNB);
  lstm_policy_kernel<<<NCTA, NTHR, DYNB>>>(
      (const float*)d_in[0],  // A
      (const float*)d_in[1],  // W_ih
      (const float*)d_in[2],  // W_hh
      (const float*)d_in[3],  // b_ih
      (const float*)d_in[4],  // b_hh
      (const float*)d_in[5],  // V_w
      (const float*)d_in[6],  // V_b
      (const float*)d_in[7],  // temperature
      (float*)d_out);
}